// round 16
// baseline (speedup 1.0000x reference)
#include <cuda_runtime.h>
#include <cuda_fp16.h>
#include <cstdint>
#include <cstddef>

#define B_    8
#define CIN_  64
#define COUT_ 64
#define MID_  64
#define NP_   4
#define NL_   5

// ---------------- scratch (no cudaMalloc allowed) --------------------------
// fp16 weight planes: [b][tap(9)][cout(64)][cin(64)]  (8KB per tap)
__device__ uint4 g_wh4[B_ * 9 * 64 * 8];        // 576 KB
__device__ float g_b[B_ * COUT_];

// ---------------------------------------------------------------------------
// Kernel 1: hypernetwork embed -> fp16 weight planes + bias.
// ---------------------------------------------------------------------------
__global__ __launch_bounds__(256)
void embed_kernel(
    const float* __restrict__ h,   const float* __restrict__ index,
    const float* __restrict__ conv_weight, const float* __restrict__ conv_bias,
    const float* __restrict__ W_wp, const float* __restrict__ b_wp,
    const float* __restrict__ W_wi, const float* __restrict__ b_wi,
    const float* __restrict__ W_we, const float* __restrict__ b_we,
    const float* __restrict__ W_bp, const float* __restrict__ b_bp,
    const float* __restrict__ W_bi, const float* __restrict__ b_bi)
{
    const int g  = blockIdx.x;      // cin group: cins [g*8, g*8+8)
    const int b  = blockIdx.y;
    const int jt = blockIdx.z;      // W_we row tile: rows [jt*144, jt*144+144)
    const int tid = threadIdx.x;

    __shared__ __align__(16) float w1[8 * MID_];
    __shared__ __align__(16) float Wt[144 * 68];
    __shared__ __align__(16) float hs[NP_];
    __shared__ __align__(16) float is_[NL_];

    if (tid < NP_) hs[tid] = h[b * NP_ + tid];
    if (tid < NL_) is_[tid] = index[tid];
    __syncthreads();

    for (int il = tid; il < 8 * MID_; il += 256) {
        int i = g * 8 * MID_ + il;
        float v = b_wp[i] + b_wi[i];
        #pragma unroll
        for (int p = 0; p < NP_; p++) v += hs[p] * W_wp[i * NP_ + p];
        #pragma unroll
        for (int l = 0; l < NL_; l++) v += is_[l] * W_wi[i * NL_ + l];
        w1[il] = v;
    }
    for (int idx = tid; idx < 144 * 64; idx += 256) {
        int r = idx >> 6, m = idx & 63;
        Wt[r * 68 + m] = W_we[(jt * 144 + r) * 64 + m];
    }
    __syncthreads();

    unsigned short* gw = (unsigned short*)g_wh4;

    for (int e = tid; e < 8 * 144; e += 256) {
        int cl  = e / 144;
        int jjl = e - cl * 144;
        int jj  = jt * 144 + jjl;                 // cout*9 + kk
        int cin = g * 8 + cl;
        float s = b_we[jj];
        const float4* wr  = (const float4*)&Wt[jjl * 68];
        const float4* w1r = (const float4*)&w1[cl * MID_];
        #pragma unroll
        for (int m = 0; m < 16; m++) {
            float4 a = w1r[m], q = wr[m];
            s += a.x * q.x + a.y * q.y + a.z * q.z + a.w * q.w;
        }
        int cout = jj / 9;
        int kk   = jj - cout * 9;                 // ky*3 + kx
        float wv = conv_weight[(cout * CIN_ + cin) * 9 + kk] + s;
        gw[(((size_t)(b * 9 + kk) * 64) + cout) * 64 + cin] =
            __half_as_ushort(__float2half_rn(wv));
    }

    if (g == 0 && jt == 0 && tid < COUT_) {
        float v = conv_bias[tid] + b_bp[tid] + b_bi[tid];
        #pragma unroll
        for (int p = 0; p < NP_; p++) v += hs[p] * W_bp[tid * NP_ + p];
        #pragma unroll
        for (int l = 0; l < NL_; l++) v += is_[l] * W_bi[tid * NL_ + l];
        g_b[b * COUT_ + tid] = v;
    }
}

// ---------------------------------------------------------------------------
// mma.sync / ldmatrix helpers
// ---------------------------------------------------------------------------
__device__ __forceinline__ uint32_t smem_u32(const void* p) {
    uint32_t a;
    asm("{ .reg .u64 t; cvta.to.shared.u64 t, %1; cvt.u32.u64 %0, t; }"
        : "=r"(a) : "l"(p));
    return a;
}
__device__ __forceinline__ void mma16816(float* c, const uint32_t* a,
                                         const uint32_t* b) {
    asm volatile(
        "mma.sync.aligned.m16n8k16.row.col.f32.f16.f16.f32 "
        "{%0,%1,%2,%3}, {%4,%5,%6,%7}, {%8,%9}, {%0,%1,%2,%3};"
        : "+f"(c[0]), "+f"(c[1]), "+f"(c[2]), "+f"(c[3])
        : "r"(a[0]), "r"(a[1]), "r"(a[2]), "r"(a[3]), "r"(b[0]), "r"(b[1]));
}
__device__ __forceinline__ void ldsm4(uint32_t* r, uint32_t addr) {
    asm volatile("ldmatrix.sync.aligned.m8n8.x4.shared.b16 {%0,%1,%2,%3}, [%4];"
        : "=r"(r[0]), "=r"(r[1]), "=r"(r[2]), "=r"(r[3]) : "r"(addr));
}

// ---------------------------------------------------------------------------
// Kernel 2: mma.sync conv (R15 structure; staging STS conflict-free).
// grid=(2,128,8). CTA: 2 output rows x 128 px x 64 couts, 256 thr (8 warps).
// Warp w: output row (w>>2), px quarter (w&3)*32; M=32, N=64 per warp.
// A: 4 input-row planes [130 px-rows][144B]; B: 2-slot cp.async ring.
// A-staging: thread=(plane, chunk, px-row), px-row fastest -> coalesced LDG
// AND conflict-free STS.128 (lane banks 4*(pr%8)+... tile all 32).
// Epilogue: warp-private smem transpose -> coalesced STG (R15).
// ---------------------------------------------------------------------------
#define A_RS     144
#define A_PLANE  (130 * A_RS)            // 18720
#define A_TOTAL  (4 * A_PLANE)           // 74880
#define B_SLOT   (64 * A_RS)             // 9216
#define B_OFF    A_TOTAL
#define EPI_WARP 9216                    // 64 couts * 36 floats * 4B
#define EPI_LS   36                      // floats per cout line (conflict-free)
#define BIAS_OFF (A_TOTAL + 2 * B_SLOT)  // 93312
#define SMEM_DYN (BIAS_OFF + 256)

__global__ __launch_bounds__(256, 2)
void conv_mma_kernel(const float* __restrict__ x, float* __restrict__ out)
{
    extern __shared__ __align__(16) unsigned char sm[];
    const uint32_t sb = smem_u32(sm);
    const int tid = threadIdx.x;
    const int w   = tid >> 5;
    const int l   = tid & 31;
    const int px0 = blockIdx.x * 128;
    const int y0  = blockIdx.y * 2;
    const int b   = blockIdx.z;

    float* bias_s = (float*)(sm + BIAS_OFF);
    if (tid < 64) bias_s[tid] = g_b[b * COUT_ + tid];

    // ---- B cp.async: tap t -> slot (8KB, padded 144B rows) ---------------
    auto issueB = [&](int t, int slot) {
        const char* src = (const char*)g_wh4 + (size_t)(b * 9 + t) * 8192;
        uint32_t dst0 = sb + B_OFF + slot * B_SLOT;
        #pragma unroll
        for (int i = 0; i < 2; i++) {
            int idx = tid + i * 256;      // 0..511 = row*8 + ch
            int row = idx >> 3;
            int ch  = idx & 7;
            uint32_t d = dst0 + row * A_RS + ch * 16;
            asm volatile("cp.async.cg.shared.global [%0], [%1], 16;"
                         :: "r"(d), "l"(src + ((size_t)idx << 4)));
        }
    };

    issueB(0, 0);
    asm volatile("cp.async.commit_group;" ::: "memory");

    // ---- stage A: 4 planes x 8 chunks x 130 px-rows ----------------------
    // pr fastest across lanes: coalesced LDG per cin AND conflict-free STS.128
    const float* xb = x + ((size_t)(b * CIN_) << 16);
    for (int u = tid; u < 4160; u += 256) {
        int ky  = u / 1040;                // plane (input row = y0-1+ky)
        int rem = u - ky * 1040;
        int c   = rem / 130;               // 16B chunk = cins [8c, 8c+8)
        int pr  = rem - c * 130;           // plane row; px = px0-1+pr
        int gy  = y0 - 1 + ky;
        int gx  = px0 - 1 + pr;
        bool ok = ((unsigned)gy < 256u) & ((unsigned)gx < 256u);
        const float* p = xb + ((size_t)(c * 8) << 16) + (gy << 8) + gx;
        float v[8];
        #pragma unroll
        for (int i = 0; i < 8; i++)
            v[i] = ok ? p[(size_t)i << 16] : 0.f;
        __half2 h2[4];
        #pragma unroll
        for (int i = 0; i < 4; i++)
            h2[i] = __halves2half2(__float2half_rn(v[2 * i]),
                                   __float2half_rn(v[2 * i + 1]));
        *(uint4*)(sm + ky * A_PLANE + pr * A_RS + c * 16) =
            *(uint4*)h2;
    }

    // per-lane ldmatrix offsets
    const uint32_t a_off  = (uint32_t)((l & 15) * A_RS + (l >> 4) * 16);
    const uint32_t b4_off = (uint32_t)((((l >> 4) & 1) * 8 + (l & 7)) * A_RS
                                       + ((l >> 3) & 1) * 16);

    const int wrow = w >> 2;          // output row within pair
    const int wpx  = (w & 3) * 32;    // px quarter

    float c[2][8][4];                 // [m-tile][n-tile][frag]
    #pragma unroll
    for (int mt = 0; mt < 2; mt++)
        #pragma unroll
        for (int nt = 0; nt < 8; nt++)
            #pragma unroll
            for (int q = 0; q < 4; q++) c[mt][nt][q] = 0.f;

    // ---- mainloop (2-slot ring, 2 syncs per tap) -------------------------
    #pragma unroll 1
    for (int t = 0; t < 9; t++) {
        if (t < 8) issueB(t + 1, (t + 1) & 1);
        asm volatile("cp.async.commit_group;" ::: "memory");   // empty @ t=8
        asm volatile("cp.async.wait_group 1;" ::: "memory");
        __syncthreads();   // B(t) (and A staging at t=0) visible

        const int ky = t / 3, kx = t - ky * 3;
        const uint32_t abase = sb + (wrow + ky) * A_PLANE
                             + (wpx + kx) * A_RS + a_off;
        const uint32_t bhi = sb + B_OFF + (t & 1) * B_SLOT + b4_off;

        #pragma unroll
        for (int kc = 0; kc < 4; kc++) {
            uint32_t a0[4], a1[4];
            ldsm4(a0, abase + kc * 32);
            ldsm4(a1, abase + 16 * A_RS + kc * 32);
            #pragma unroll
            for (int np = 0; np < 4; np++) {
                uint32_t bh[4];
                ldsm4(bh, bhi + np * 16 * A_RS + kc * 32);
                mma16816(c[0][2 * np + 0], a0, bh + 0);
                mma16816(c[0][2 * np + 1], a0, bh + 2);
                mma16816(c[1][2 * np + 0], a1, bh + 0);
                mma16816(c[1][2 * np + 1], a1, bh + 2);
            }
        }
        __syncthreads();   // slot reads done before re-fill
    }

    // ---- epilogue: warp-private transpose in freed A-plane smem ----------
    __syncthreads();   // all warps done reading A planes / B slots
    float* epi = (float*)(sm + w * EPI_WARP);   // this warp's 64x36 region
    const int gg  = l >> 2, tig = l & 3;
    #pragma unroll
    for (int mt = 0; mt < 2; mt++) {
        #pragma unroll
        for (int nt = 0; nt < 8; nt++) {
            int c0  = nt * 8 + tig * 2;
            int pxl = mt * 16 + gg;
            epi[(c0 + 0) * EPI_LS + pxl]     = c[mt][nt][0];
            epi[(c0 + 1) * EPI_LS + pxl]     = c[mt][nt][1];
            epi[(c0 + 0) * EPI_LS + pxl + 8] = c[mt][nt][2];
            epi[(c0 + 1) * EPI_LS + pxl + 8] = c[mt][nt][3];
        }
    }
    __syncwarp();
    // coalesced store: 64 couts, each a 32-px (128B) contiguous line
    float* ob = out + (((size_t)b * COUT_) << 16) + ((y0 + wrow) << 8)
              + px0 + wpx;
    #pragma unroll 4
    for (int cc = 0; cc < 64; cc++) {
        float v = epi[cc * EPI_LS + l] + bias_s[cc];
        ob[((size_t)cc << 16) + l] = v;
    }
}

// ---------------------------------------------------------------------------
extern "C" void kernel_launch(void* const* d_in, const int* in_sizes, int n_in,
                              void* d_out, int out_size)
{
    const float* x           = (const float*)d_in[0];
    const float* h           = (const float*)d_in[1];
    const float* index       = (const float*)d_in[2];
    const float* conv_weight = (const float*)d_in[3];
    const float* conv_bias   = (const float*)d_in[4];
    const float* W_wp        = (const float*)d_in[5];
    const float* b_wp        = (const float*)d_in[6];
    const float* W_wi        = (const float*)d_in[7];
    const float* b_wi        = (const float*)d_in[8];
    const float* W_we        = (const float*)d_in[9];
    const float* b_we        = (const float*)d_in[10];
    const float* W_bp        = (const float*)d_in[11];
    const float* b_bp        = (const float*)d_in[12];
    const float* W_bi        = (const float*)d_in[13];
    const float* b_bi        = (const float*)d_in[14];
    float* out = (float*)d_out;

    cudaFuncSetAttribute(conv_mma_kernel,
                         cudaFuncAttributeMaxDynamicSharedMemorySize, SMEM_DYN);

    dim3 g1(8, 8, 4);
    embed_kernel<<<g1, 256>>>(h, index, conv_weight, conv_bias,
                              W_wp, b_wp, W_wi, b_wi, W_we, b_we,
                              W_bp, b_bp, W_bi, b_bi);

    dim3 g2(2, 128, B_);
    conv_mma_kernel<<<g2, 256, SMEM_DYN>>>(x, out);
}

// round 17
// speedup vs baseline: 1.1352x; 1.1352x over previous
#include <cuda_runtime.h>
#include <cuda_fp16.h>
#include <cstdint>
#include <cstddef>

#define B_    8
#define CIN_  64
#define COUT_ 64
#define MID_  64
#define NP_   4
#define NL_   5

// ---------------- scratch (no cudaMalloc allowed) --------------------------
// fp16 weight planes: [b][tap(9)][cout(64)][cin(64)]  (8KB per tap)
__device__ uint4 g_wh4[B_ * 9 * 64 * 8];        // 576 KB
__device__ float g_b[B_ * COUT_];

// ---------------------------------------------------------------------------
// Kernel 1: hypernetwork embed -> fp16 weight planes + bias.
// Store-coalesced: 8-lane groups write 8 consecutive cins (16B) per jj.
// w1/Wt stride 68 -> conflict-free float4 LDS.
// ---------------------------------------------------------------------------
__global__ __launch_bounds__(256)
void embed_kernel(
    const float* __restrict__ h,   const float* __restrict__ index,
    const float* __restrict__ conv_weight, const float* __restrict__ conv_bias,
    const float* __restrict__ W_wp, const float* __restrict__ b_wp,
    const float* __restrict__ W_wi, const float* __restrict__ b_wi,
    const float* __restrict__ W_we, const float* __restrict__ b_we,
    const float* __restrict__ W_bp, const float* __restrict__ b_bp,
    const float* __restrict__ W_bi, const float* __restrict__ b_bi)
{
    const int g  = blockIdx.x;      // cin group: cins [g*8, g*8+8)
    const int b  = blockIdx.y;
    const int jt = blockIdx.z;      // W_we row tile: rows [jt*144, jt*144+144)
    const int tid = threadIdx.x;

    __shared__ __align__(16) float w1[8 * 68];       // stride 68 (CF lanes)
    __shared__ __align__(16) float Wt[144 * 68];
    __shared__ __align__(16) float hs[NP_];
    __shared__ __align__(16) float is_[NL_];

    if (tid < NP_) hs[tid] = h[b * NP_ + tid];
    if (tid < NL_) is_[tid] = index[tid];
    __syncthreads();

    for (int il = tid; il < 8 * MID_; il += 256) {
        int cl = il >> 6, m = il & 63;
        int i  = g * 8 * MID_ + il;
        float v = b_wp[i] + b_wi[i];
        #pragma unroll
        for (int p = 0; p < NP_; p++) v += hs[p] * W_wp[i * NP_ + p];
        #pragma unroll
        for (int l = 0; l < NL_; l++) v += is_[l] * W_wi[i * NL_ + l];
        w1[cl * 68 + m] = v;
    }
    for (int idx = tid; idx < 144 * 64; idx += 256) {
        int r = idx >> 6, m = idx & 63;
        Wt[r * 68 + m] = W_we[(jt * 144 + r) * 64 + m];
    }
    __syncthreads();

    unsigned short* gw = (unsigned short*)g_wh4;

    for (int e = tid; e < 8 * 144; e += 256) {
        int cl  = e & 7;                          // FAST index -> coalesced st
        int jjl = e >> 3;
        int jj  = jt * 144 + jjl;                 // cout*9 + kk
        int cin = g * 8 + cl;
        float s = b_we[jj];
        const float4* wr  = (const float4*)&Wt[jjl * 68];
        const float4* w1r = (const float4*)&w1[cl * 68];
        #pragma unroll
        for (int m = 0; m < 16; m++) {
            float4 a = w1r[m], q = wr[m];
            s += a.x * q.x + a.y * q.y + a.z * q.z + a.w * q.w;
        }
        int cout = jj / 9;
        int kk   = jj - cout * 9;                 // ky*3 + kx
        float wv = conv_weight[(cout * CIN_ + cin) * 9 + kk] + s;
        gw[(((size_t)(b * 9 + kk) * 64) + cout) * 64 + cin] =
            __half_as_ushort(__float2half_rn(wv));
    }

    if (g == 0 && jt == 0 && tid < COUT_) {
        float v = conv_bias[tid] + b_bp[tid] + b_bi[tid];
        #pragma unroll
        for (int p = 0; p < NP_; p++) v += hs[p] * W_bp[tid * NP_ + p];
        #pragma unroll
        for (int l = 0; l < NL_; l++) v += is_[l] * W_bi[tid * NL_ + l];
        g_b[b * COUT_ + tid] = v;
    }
}

// ---------------------------------------------------------------------------
// mma.sync / ldmatrix helpers
// ---------------------------------------------------------------------------
__device__ __forceinline__ uint32_t smem_u32(const void* p) {
    uint32_t a;
    asm("{ .reg .u64 t; cvta.to.shared.u64 t, %1; cvt.u32.u64 %0, t; }"
        : "=r"(a) : "l"(p));
    return a;
}
__device__ __forceinline__ void mma16816(float* c, const uint32_t* a,
                                         const uint32_t* b) {
    asm volatile(
        "mma.sync.aligned.m16n8k16.row.col.f32.f16.f16.f32 "
        "{%0,%1,%2,%3}, {%4,%5,%6,%7}, {%8,%9}, {%0,%1,%2,%3};"
        : "+f"(c[0]), "+f"(c[1]), "+f"(c[2]), "+f"(c[3])
        : "r"(a[0]), "r"(a[1]), "r"(a[2]), "r"(a[3]), "r"(b[0]), "r"(b[1]));
}
__device__ __forceinline__ void ldsm4(uint32_t* r, uint32_t addr) {
    asm volatile("ldmatrix.sync.aligned.m8n8.x4.shared.b16 {%0,%1,%2,%3}, [%4];"
        : "=r"(r[0]), "=r"(r[1]), "=r"(r[2]), "=r"(r[3]) : "r"(addr));
}

// ---------------------------------------------------------------------------
// Kernel 2: mma.sync conv. grid=(2,128,8). R15 structure with a 3-slot B
// ring -> ONE __syncthreads per tap. CTA: 2 rows x 128 px x 64 couts,
// 256 thr. A: 4 planes [130 rows][144B] (R15 float2 staging); epilogue:
// warp-private smem transpose -> coalesced STG (R15).
// ---------------------------------------------------------------------------
#define A_RS     144
#define A_PLANE  (130 * A_RS)            // 18720
#define A_TOTAL  (4 * A_PLANE)           // 74880
#define B_SLOT   (64 * A_RS)             // 9216
#define B_OFF    A_TOTAL
#define EPI_WARP 9216                    // 64 couts * 36 floats * 4B
#define EPI_LS   36
#define BIAS_OFF (A_TOTAL + 3 * B_SLOT)  // 102528
#define SMEM_DYN (BIAS_OFF + 256)

__global__ __launch_bounds__(256, 2)
void conv_mma_kernel(const float* __restrict__ x, float* __restrict__ out)
{
    extern __shared__ __align__(16) unsigned char sm[];
    const uint32_t sb = smem_u32(sm);
    const int tid = threadIdx.x;
    const int w   = tid >> 5;
    const int l   = tid & 31;
    const int px0 = blockIdx.x * 128;
    const int y0  = blockIdx.y * 2;
    const int b   = blockIdx.z;

    float* bias_s = (float*)(sm + BIAS_OFF);
    if (tid < 64) bias_s[tid] = g_b[b * COUT_ + tid];

    // ---- B cp.async: tap t -> slot s (8KB, padded 144B rows) + commit ----
    auto issueB = [&](int t, int s) {
        const char* src = (const char*)g_wh4 + (size_t)(b * 9 + t) * 8192;
        uint32_t dst0 = sb + B_OFF + s * B_SLOT;
        #pragma unroll
        for (int i = 0; i < 2; i++) {
            int idx = tid + i * 256;      // 0..511 = row*8 + ch
            int row = idx >> 3;
            int ch  = idx & 7;
            uint32_t d = dst0 + row * A_RS + ch * 16;
            asm volatile("cp.async.cg.shared.global [%0], [%1], 16;"
                         :: "r"(d), "l"(src + ((size_t)idx << 4)));
        }
        asm volatile("cp.async.commit_group;" ::: "memory");
    };

    issueB(0, 0);
    issueB(1, 1);

    // ---- stage A (R15): 4 planes; plane rows 0..129 = px0-1..px0+128 -----
    const float* xb = x + ((size_t)(b * CIN_) << 16);
    for (int u = tid; u < 8192; u += 256) {
        int ky  = u >> 11;                 // input row = y0-1+ky
        int rem = u & 2047;
        int cp  = rem >> 6;                // cin pair
        int p2  = rem & 63;                // px pair (fastest -> coalesced LDG)
        int gy  = y0 - 1 + ky;
        int gx  = px0 + 2 * p2;
        float2 v0 = make_float2(0.f, 0.f), v1 = make_float2(0.f, 0.f);
        if ((unsigned)gy < 256u) {
            const float* p = xb + ((size_t)(cp * 2) << 16) + (gy << 8) + gx;
            v0 = *(const float2*)p;
            v1 = *(const float2*)(p + ((size_t)1 << 16));
        }
        unsigned char* pl = sm + ky * A_PLANE + cp * 4;
        *(__half2*)(pl + (1 + 2 * p2) * A_RS) =
            __halves2half2(__float2half_rn(v0.x), __float2half_rn(v1.x));
        *(__half2*)(pl + (2 + 2 * p2) * A_RS) =
            __halves2half2(__float2half_rn(v0.y), __float2half_rn(v1.y));
    }
    // edges: plane rows 0 (px0-1) and 129 (px0+128)
    {
        int ky   = tid >> 6;
        int rem  = tid & 63;
        int side = rem >> 5;
        int cp   = rem & 31;
        int gy   = y0 - 1 + ky;
        int gx   = side ? (px0 + 128) : (px0 - 1);
        int r    = side ? 129 : 0;
        float a0 = 0.f, a1 = 0.f;
        if ((unsigned)gy < 256u && (unsigned)gx < 256u) {
            const float* p = xb + ((size_t)(cp * 2) << 16) + (gy << 8) + gx;
            a0 = p[0];
            a1 = p[(size_t)1 << 16];
        }
        *(__half2*)(sm + ky * A_PLANE + r * A_RS + cp * 4) =
            __halves2half2(__float2half_rn(a0), __float2half_rn(a1));
    }

    // per-lane ldmatrix offsets
    const uint32_t a_off  = (uint32_t)((l & 15) * A_RS + (l >> 4) * 16);
    const uint32_t b4_off = (uint32_t)((((l >> 4) & 1) * 8 + (l & 7)) * A_RS
                                       + ((l >> 3) & 1) * 16);

    const int wrow = w >> 2;          // output row within pair
    const int wpx  = (w & 3) * 32;    // px quarter

    float c[2][8][4];                 // [m-tile][n-tile][frag]
    #pragma unroll
    for (int mt = 0; mt < 2; mt++)
        #pragma unroll
        for (int nt = 0; nt < 8; nt++)
            #pragma unroll
            for (int q = 0; q < 4; q++) c[mt][nt][q] = 0.f;

    // ---- mainloop: 3-slot ring, ONE barrier per tap ----------------------
    #pragma unroll 1
    for (int t = 0; t < 9; t++) {
        asm volatile("cp.async.wait_group 1;" ::: "memory");  // B(t) landed
        __syncthreads();  // B(t)+(A @t=0) visible; all warps past tap t-1
        if (t + 2 < 9) issueB(t + 2, (t + 2) % 3);   // refills slot (t-1)%3
        else asm volatile("cp.async.commit_group;" ::: "memory");  // empty

        const int ky = t / 3, kx = t - ky * 3;
        const uint32_t abase = sb + (wrow + ky) * A_PLANE
                             + (wpx + kx) * A_RS + a_off;
        const uint32_t bhi = sb + B_OFF + (t % 3) * B_SLOT + b4_off;

        #pragma unroll
        for (int kc = 0; kc < 4; kc++) {
            uint32_t a0[4], a1[4];
            ldsm4(a0, abase + kc * 32);
            ldsm4(a1, abase + 16 * A_RS + kc * 32);
            #pragma unroll
            for (int np = 0; np < 4; np++) {
                uint32_t bh[4];
                ldsm4(bh, bhi + np * 16 * A_RS + kc * 32);
                mma16816(c[0][2 * np + 0], a0, bh + 0);
                mma16816(c[0][2 * np + 1], a0, bh + 2);
                mma16816(c[1][2 * np + 0], a1, bh + 0);
                mma16816(c[1][2 * np + 1], a1, bh + 2);
            }
        }
    }

    // ---- epilogue: warp-private transpose in freed A-plane smem ----------
    __syncthreads();   // all warps done reading A planes / B slots
    float* epi = (float*)(sm + w * EPI_WARP);   // this warp's 64x36 region
    const int gg  = l >> 2, tig = l & 3;
    #pragma unroll
    for (int mt = 0; mt < 2; mt++) {
        #pragma unroll
        for (int nt = 0; nt < 8; nt++) {
            int c0  = nt * 8 + tig * 2;
            int pxl = mt * 16 + gg;
            epi[(c0 + 0) * EPI_LS + pxl]     = c[mt][nt][0];
            epi[(c0 + 1) * EPI_LS + pxl]     = c[mt][nt][1];
            epi[(c0 + 0) * EPI_LS + pxl + 8] = c[mt][nt][2];
            epi[(c0 + 1) * EPI_LS + pxl + 8] = c[mt][nt][3];
        }
    }
    __syncwarp();
    // coalesced store: 64 couts, each a 32-px (128B) contiguous line
    float* ob = out + (((size_t)b * COUT_) << 16) + ((y0 + wrow) << 8)
              + px0 + wpx;
    #pragma unroll 4
    for (int cc = 0; cc < 64; cc++) {
        float v = epi[cc * EPI_LS + l] + bias_s[cc];
        ob[((size_t)cc << 16) + l] = v;
    }
}

// ---------------------------------------------------------------------------
extern "C" void kernel_launch(void* const* d_in, const int* in_sizes, int n_in,
                              void* d_out, int out_size)
{
    const float* x           = (const float*)d_in[0];
    const float* h           = (const float*)d_in[1];
    const float* index       = (const float*)d_in[2];
    const float* conv_weight = (const float*)d_in[3];
    const float* conv_bias   = (const float*)d_in[4];
    const float* W_wp        = (const float*)d_in[5];
    const float* b_wp        = (const float*)d_in[6];
    const float* W_wi        = (const float*)d_in[7];
    const float* b_wi        = (const float*)d_in[8];
    const float* W_we        = (const float*)d_in[9];
    const float* b_we        = (const float*)d_in[10];
    const float* W_bp        = (const float*)d_in[11];
    const float* b_bp        = (const float*)d_in[12];
    const float* W_bi        = (const float*)d_in[13];
    const float* b_bi        = (const float*)d_in[14];
    float* out = (float*)d_out;

    cudaFuncSetAttribute(conv_mma_kernel,
                         cudaFuncAttributeMaxDynamicSharedMemorySize, SMEM_DYN);

    dim3 g1(8, 8, 4);
    embed_kernel<<<g1, 256>>>(h, index, conv_weight, conv_bias,
                              W_wp, b_wp, W_wi, b_wi, W_we, b_we,
                              W_bp, b_bp, W_bi, b_bi);

    dim3 g2(2, 128, B_);
    conv_mma_kernel<<<g2, 256, SMEM_DYN>>>(x, out);
}